// round 14
// baseline (speedup 1.0000x reference)
#include <cuda_runtime.h>
#include <cuda_bf16.h>
#include <cstdint>

#define BATCH 128
#define SEQLEN 8194
#define NCH 32
#define SEC 4
#define DDIM 128
#define NL 2048
#define NTILE 128
#define NT (NL / NTILE)
#define TPB 512
#define PITCH 136   // bf16 elements per smem row (128 + 8 pad)
#define PSTRIDE 32  // padded letter stride in P LUT

// scratch
__device__ float g_e[BATCH * NL];
__device__ float g_w[BATCH * NL];
__device__ float g_H[(size_t)BATCH * DDIM * NL];        // 134 MB fp32 H
__device__ __nv_bfloat16 g_Whi[DDIM * PITCH];           // pre-pitched W_a hi
__device__ __nv_bfloat16 g_Wlo[DDIM * PITCH];           // pre-pitched W_a lo
__device__ float g_P[NCH * 3 * PSTRIDE];                // conv letter LUT (bias folded)

// ---------------- helpers ----------------
__device__ __forceinline__ uint32_t smem_u32(const void* p) {
    uint32_t a;
    asm("{ .reg .u64 t; cvta.to.shared.u64 t, %1; cvt.u32.u64 %0, t; }" : "=r"(a) : "l"(p));
    return a;
}

#define LDSM_X4(r, addr) \
    asm volatile("ldmatrix.sync.aligned.m8n8.x4.shared.b16 {%0,%1,%2,%3}, [%4];" \
        : "=r"((r)[0]), "=r"((r)[1]), "=r"((r)[2]), "=r"((r)[3]) : "r"(addr))

#define LDSM_X4_T(r, addr) \
    asm volatile("ldmatrix.sync.aligned.m8n8.x4.trans.shared.b16 {%0,%1,%2,%3}, [%4];" \
        : "=r"((r)[0]), "=r"((r)[1]), "=r"((r)[2]), "=r"((r)[3]) : "r"(addr))

#define MMA_BF16(c, a, b0, b1) \
    asm volatile("mma.sync.aligned.m16n8k16.row.col.f32.bf16.bf16.f32 " \
        "{%0,%1,%2,%3}, {%4,%5,%6,%7}, {%8,%9}, {%0,%1,%2,%3};" \
        : "+f"((c)[0]), "+f"((c)[1]), "+f"((c)[2]), "+f"((c)[3]) \
        : "r"((a)[0]), "r"((a)[1]), "r"((a)[2]), "r"((a)[3]), "r"(b0), "r"(b1))

__device__ __forceinline__ float ftanh(float x) {
    float r;
    asm("tanh.approx.f32 %0, %1;" : "=f"(r) : "f"(x));
    return r;
}

// SMEM byte offsets (k1): tiles are [128][PITCH] bf16 = 34816 B each
#define OFF_AHI 0
#define OFF_ALO 34816
#define OFF_BHI 69632
#define OFF_BLO 104448
#define OFF_SP   139264              // P LUT: 3072 f = 12288 B
#define OFF_SV   (OFF_SP + 12288)    // 128 f
#define OFF_SSEQ (OFF_SV + 512)      // 520 i
#define OFF_EP   (OFF_SSEQ + 2080)   // 4 x 128 f
#define SM1_BYTES (OFF_EP + 2048)

// ---------------------------------------------------------------------------
// Kernel 0: one-time prep: W_a -> bf16 hi/lo pre-pitched; conv LUT w/ bias
//   P[c][k][l] = sum_i emb[l*5+i] * cw[c*15 + i*3 + k]  (+ cb[c] at k==0)
// ---------------------------------------------------------------------------
__global__ __launch_bounds__(256) void k0_prep(
    const float* __restrict__ Wa, const float* __restrict__ emb,
    const float* __restrict__ cw, const float* __restrict__ cb)
{
    int i = blockIdx.x * 256 + threadIdx.x;
    if (i < DDIM * DDIM) {
        float v = Wa[i];
        __nv_bfloat16 h = __float2bfloat16(v);
        __nv_bfloat16 l = __float2bfloat16(v - __bfloat162float(h));
        int d = i >> 7, e = i & 127;
        g_Whi[d * PITCH + e] = h;
        g_Wlo[d * PITCH + e] = l;
    }
    int j = i - DDIM * DDIM;
    if (j >= 0 && j < NCH * 3 * 26) {
        int c = j / (3 * 26), k = (j / 26) % 3, l = j % 26;
        float s = (k == 0) ? cb[c] : 0.f;
        #pragma unroll
        for (int i2 = 0; i2 < 5; i2++)
            s += emb[l * 5 + i2] * cw[c * 15 + i2 * 3 + k];
        g_P[(c * 3 + k) * PSTRIDE + l] = s;
    }
}

// ---------------------------------------------------------------------------
// Kernel 1: LUT-conv (paired n) -> H + bf16 hi/lo B tiles -> 3-term HMMA -> e
// 16 warps: 4 (m) x 4 (n), warp tile 32x32
// ---------------------------------------------------------------------------
__global__ __launch_bounds__(TPB, 1) void k1_conv_attn(
    const int* __restrict__ seq, const float* __restrict__ va)
{
    extern __shared__ char sm[];
    const uint32_t smb = smem_u32(sm);
    float* sP   = (float*)(sm + OFF_SP);
    float* sv   = (float*)(sm + OFF_SV);
    int*   sseq = (int*)(sm + OFF_SSEQ);
    float* ep   = (float*)(sm + OFF_EP);

    const int tid = threadIdx.x;
    const int wid = tid >> 5, lane = tid & 31;
    const int t = blockIdx.x, b = blockIdx.y;

    // A tiles: straight copy of pre-converted, pre-pitched W_a (L2-resident)
    {
        const uint4* Ah = (const uint4*)g_Whi;
        const uint4* Al = (const uint4*)g_Wlo;
        uint4* dAh = (uint4*)(sm + OFF_AHI);
        uint4* dAl = (uint4*)(sm + OFF_ALO);
        #pragma unroll
        for (int i = tid; i < DDIM * PITCH / 8; i += TPB) {
            dAh[i] = Ah[i];
            dAl[i] = Al[i];
        }
    }

    // small tables
    for (int i = tid; i < NCH * 3 * PSTRIDE; i += TPB) sP[i] = g_P[i];
    if (tid < 128) sv[tid] = va[tid];
    for (int i = tid; i < 4 * 130; i += TPB) {
        int s = i / 130, j = i % 130;
        sseq[i] = seq[b * SEQLEN + s * NL + t * NTILE + j];
    }
    __syncthreads();

    // conv via LUT + relu, paired n -> g_H (float2) + B hi/lo tiles (bf16x2)
    {
        const int n0 = (tid & 63) * 2;
        const int cs0 = tid >> 6;   // 0..7
        float* Hbase = g_H + (size_t)b * DDIM * NL + (size_t)t * NTILE + n0;
        #pragma unroll
        for (int s = 0; s < 4; s++) {
            const int l0 = sseq[s * 130 + n0];
            const int l1 = sseq[s * 130 + n0 + 1];
            const int l2 = sseq[s * 130 + n0 + 2];
            const int l3 = sseq[s * 130 + n0 + 3];
            #pragma unroll
            for (int jj = 0; jj < 4; jj++) {
                const int c = cs0 + 8 * jj;
                const float* Pc = sP + c * 3 * PSTRIDE;
                float a0 = Pc[l0] + Pc[PSTRIDE + l1] + Pc[2 * PSTRIDE + l2];
                float a1 = Pc[l1] + Pc[PSTRIDE + l2] + Pc[2 * PSTRIDE + l3];
                a0 = fmaxf(a0, 0.f);
                a1 = fmaxf(a1, 0.f);
                const int e = c * 4 + s;
                *(float2*)&Hbase[(size_t)e * NL] = make_float2(a0, a1);
                __nv_bfloat162 hi2 = __float22bfloat162_rn(make_float2(a0, a1));
                __nv_bfloat162 lo2 = __float22bfloat162_rn(
                    make_float2(a0 - __bfloat162float(hi2.x),
                                a1 - __bfloat162float(hi2.y)));
                uint32_t o = (uint32_t)(e * PITCH + n0) * 2;
                *(__nv_bfloat162*)(sm + OFF_BHI + o) = hi2;
                *(__nv_bfloat162*)(sm + OFF_BLO + o) = lo2;
            }
        }
    }
    __syncthreads();

    // ------- GEMM: M = Ahi*Bhi + Ahi*Blo + Alo*Bhi, fp32 accum -------------
    const int wm = (wid & 3) * 32;
    const int wn = (wid >> 2) * 32;
    const int qd = lane >> 3, r8 = lane & 7;

    float c[2][4][4];
    #pragma unroll
    for (int mt = 0; mt < 2; mt++)
        #pragma unroll
        for (int nt = 0; nt < 4; nt++)
            #pragma unroll
            for (int q = 0; q < 4; q++) c[mt][nt][q] = 0.f;

    #pragma unroll
    for (int ks = 0; ks < 8; ks++) {
        const int k0 = ks * 16;
        uint32_t ahi[2][4], alo[2][4];
        #pragma unroll
        for (int mt = 0; mt < 2; mt++) {
            uint32_t addr = smb + OFF_AHI +
                (uint32_t)((wm + mt * 16 + r8 + (qd & 1) * 8) * PITCH + k0 + (qd >> 1) * 8) * 2;
            LDSM_X4(ahi[mt], addr);
            LDSM_X4(alo[mt], addr + (OFF_ALO - OFF_AHI));
        }
        uint32_t bhi[2][4], blo[2][4];
        #pragma unroll
        for (int nb = 0; nb < 2; nb++) {
            uint32_t addr = smb + OFF_BHI +
                (uint32_t)((k0 + r8 + (qd & 1) * 8) * PITCH + wn + nb * 16 + (qd >> 1) * 8) * 2;
            LDSM_X4_T(bhi[nb], addr);
            LDSM_X4_T(blo[nb], addr + (OFF_BLO - OFF_BHI));
        }
        #pragma unroll
        for (int mt = 0; mt < 2; mt++)
            #pragma unroll
            for (int nt = 0; nt < 4; nt++) {
                const int nb = nt >> 1, p = (nt & 1) * 2;
                MMA_BF16(c[mt][nt], ahi[mt], bhi[nb][p], bhi[nb][p + 1]);
                MMA_BF16(c[mt][nt], ahi[mt], blo[nb][p], blo[nb][p + 1]);
                MMA_BF16(c[mt][nt], alo[mt], bhi[nb][p], bhi[nb][p + 1]);
            }
    }

    // ---------------- epilogue: e[n] = sum_d v[d]*tanh(M[d][n]) ------------
    {
        const int g = lane >> 2, tq = lane & 3;
        #pragma unroll
        for (int nt = 0; nt < 4; nt++) {
            #pragma unroll
            for (int j = 0; j < 2; j++) {
                float s = 0.f;
                #pragma unroll
                for (int mt = 0; mt < 2; mt++) {
                    int d0 = wm + mt * 16 + g;
                    s += sv[d0]     * ftanh(c[mt][nt][j]);
                    s += sv[d0 + 8] * ftanh(c[mt][nt][2 + j]);
                }
                s += __shfl_xor_sync(0xffffffffu, s, 4);
                s += __shfl_xor_sync(0xffffffffu, s, 8);
                s += __shfl_xor_sync(0xffffffffu, s, 16);
                if (g == 0)
                    ep[(wid & 3) * 128 + wn + nt * 8 + tq * 2 + j] = s;
            }
        }
    }
    __syncthreads();
    if (tid < 128)
        g_e[b * NL + t * NTILE + tid] =
            (ep[tid] + ep[128 + tid]) + (ep[256 + tid] + ep[384 + tid]);
}

// ---------------------------------------------------------------------------
// Kernel 2: stable softmax per batch
// ---------------------------------------------------------------------------
__global__ __launch_bounds__(256) void k2_softmax()
{
    __shared__ float red[256];
    const int b = blockIdx.x, tid = threadIdx.x;
    float vals[8];
    float vmax = -1e30f;
    #pragma unroll
    for (int j = 0; j < 8; j++) {
        vals[j] = g_e[b * NL + tid + 256 * j];
        vmax = fmaxf(vmax, vals[j]);
    }
    red[tid] = vmax; __syncthreads();
    for (int off = 128; off > 0; off >>= 1) {
        if (tid < off) red[tid] = fmaxf(red[tid], red[tid + off]);
        __syncthreads();
    }
    vmax = red[0]; __syncthreads();
    float ssum = 0.f;
    #pragma unroll
    for (int j = 0; j < 8; j++) { vals[j] = __expf(vals[j] - vmax); ssum += vals[j]; }
    red[tid] = ssum; __syncthreads();
    for (int off = 128; off > 0; off >>= 1) {
        if (tid < off) red[tid] += red[tid + off];
        __syncthreads();
    }
    float inv = __fdividef(1.f, red[0]);
    #pragma unroll
    for (int j = 0; j < 8; j++) g_w[b * NL + tid + 256 * j] = vals[j] * inv;
}

// ---------------------------------------------------------------------------
// Kernel 3: ctx[b][d] = sum_n w[b][n] * H[b][d][n]   (DRAM-bound GEMV)
// grid (16, BATCH): 8 d-rows per CTA, one warp per d-row; streaming H loads
// ---------------------------------------------------------------------------
__global__ __launch_bounds__(256, 4) void k3_ctx(float* __restrict__ out)
{
    __shared__ float sw_[NL];
    const int tid = threadIdx.x;
    const int dc = blockIdx.x, b = blockIdx.y;

    const float4* Wg = (const float4*)(g_w + b * NL);
    float4* Ws = (float4*)sw_;
    #pragma unroll
    for (int i = tid; i < NL / 4; i += 256) Ws[i] = Wg[i];
    __syncthreads();

    const int dl = tid >> 5, hh = tid & 31;
    const int d = dc * 8 + dl;
    const float4* Hp = (const float4*)(g_H + (size_t)(b * DDIM + d) * NL);
    float s = 0.f;
    #pragma unroll
    for (int j = 0; j < 16; j++) {
        int n4 = hh + j * 32;
        float4 hv = __ldcs(Hp + n4);
        float4 wv = Ws[n4];
        s += hv.x * wv.x + hv.y * wv.y + hv.z * wv.z + hv.w * wv.w;
    }
    #pragma unroll
    for (int off = 16; off > 0; off >>= 1) s += __shfl_down_sync(0xffffffffu, s, off);
    if (hh == 0) out[b * DDIM + d] = s;
}

// ---------------------------------------------------------------------------
extern "C" void kernel_launch(void* const* d_in, const int* in_sizes, int n_in,
                              void* d_out, int out_size)
{
    const int*   seq = (const int*)d_in[0];
    const float* emb = (const float*)d_in[1];
    const float* cw  = (const float*)d_in[2];
    const float* cb  = (const float*)d_in[3];
    const float* Wa  = (const float*)d_in[4];
    const float* va  = (const float*)d_in[5];
    float* out = (float*)d_out;

    cudaFuncSetAttribute(k1_conv_attn, cudaFuncAttributeMaxDynamicSharedMemorySize, SM1_BYTES);

    k0_prep<<<(DDIM * DDIM + NCH * 3 * 26 + 255) / 256, 256>>>(Wa, emb, cw, cb);
    k1_conv_attn<<<dim3(NT, BATCH), TPB, SM1_BYTES>>>(seq, va);
    k2_softmax<<<BATCH, 256>>>();
    k3_ctx<<<dim3(16, BATCH), 256>>>(out);
}

// round 17
// speedup vs baseline: 1.4011x; 1.4011x over previous
#include <cuda_runtime.h>
#include <cuda_fp16.h>
#include <cstdint>

#define BATCH 128
#define SEQLEN 8194
#define NCH 32
#define SEC 4
#define DDIM 128
#define NL 2048
#define NTILE 128
#define NT (NL / NTILE)
#define TPB 512
#define PITCH 136   // fp16 elements per smem row (128 + 8 pad)
#define PSTRIDE 32  // padded letter stride in P LUT

// scratch
__device__ float g_e[BATCH * NL];
__device__ float g_w[BATCH * NL];
__device__ float g_H[(size_t)BATCH * DDIM * NL];   // 134 MB fp32 H
__device__ __half g_Wh[DDIM * PITCH];              // pre-pitched W_a fp16
__device__ float g_P[NCH * 3 * PSTRIDE];           // conv letter LUT (bias folded)

// ---------------- helpers ----------------
__device__ __forceinline__ uint32_t smem_u32(const void* p) {
    uint32_t a;
    asm("{ .reg .u64 t; cvta.to.shared.u64 t, %1; cvt.u32.u64 %0, t; }" : "=r"(a) : "l"(p));
    return a;
}

#define LDSM_X4(r, addr) \
    asm volatile("ldmatrix.sync.aligned.m8n8.x4.shared.b16 {%0,%1,%2,%3}, [%4];" \
        : "=r"((r)[0]), "=r"((r)[1]), "=r"((r)[2]), "=r"((r)[3]) : "r"(addr))

#define LDSM_X4_T(r, addr) \
    asm volatile("ldmatrix.sync.aligned.m8n8.x4.trans.shared.b16 {%0,%1,%2,%3}, [%4];" \
        : "=r"((r)[0]), "=r"((r)[1]), "=r"((r)[2]), "=r"((r)[3]) : "r"(addr))

#define MMA_F16(c, a, b0, b1) \
    asm volatile("mma.sync.aligned.m16n8k16.row.col.f32.f16.f16.f32 " \
        "{%0,%1,%2,%3}, {%4,%5,%6,%7}, {%8,%9}, {%0,%1,%2,%3};" \
        : "+f"((c)[0]), "+f"((c)[1]), "+f"((c)[2]), "+f"((c)[3]) \
        : "r"((a)[0]), "r"((a)[1]), "r"((a)[2]), "r"((a)[3]), "r"(b0), "r"(b1))

__device__ __forceinline__ float ftanh(float x) {
    float r;
    asm("tanh.approx.f32 %0, %1;" : "=f"(r) : "f"(x));
    return r;
}

// SMEM byte offsets (k1): A/B tiles are [128][PITCH] fp16 = 34816 B each
#define OFF_A   0
#define OFF_B   34816
#define OFF_SP   69632               // P LUT: 3072 f = 12288 B
#define OFF_SV   (OFF_SP + 12288)    // 128 f
#define OFF_SSEQ (OFF_SV + 512)      // 520 i
#define OFF_EP   (OFF_SSEQ + 2080)   // 4 x 128 f
#define SM1_BYTES (OFF_EP + 2048)

// ---------------------------------------------------------------------------
// Kernel 0: one-time prep: W_a -> fp16 pre-pitched; conv LUT w/ bias
//   P[c][k][l] = sum_i emb[l*5+i] * cw[c*15 + i*3 + k]  (+ cb[c] at k==0)
// ---------------------------------------------------------------------------
__global__ __launch_bounds__(256) void k0_prep(
    const float* __restrict__ Wa, const float* __restrict__ emb,
    const float* __restrict__ cw, const float* __restrict__ cb)
{
    int i = blockIdx.x * 256 + threadIdx.x;
    if (i < DDIM * DDIM) {
        int d = i >> 7, e = i & 127;
        g_Wh[d * PITCH + e] = __float2half_rn(Wa[i]);
    }
    int j = i - DDIM * DDIM;
    if (j >= 0 && j < NCH * 3 * 26) {
        int c = j / (3 * 26), k = (j / 26) % 3, l = j % 26;
        float s = (k == 0) ? cb[c] : 0.f;
        #pragma unroll
        for (int i2 = 0; i2 < 5; i2++)
            s += emb[l * 5 + i2] * cw[c * 15 + i2 * 3 + k];
        g_P[(c * 3 + k) * PSTRIDE + l] = s;
    }
}

// ---------------------------------------------------------------------------
// Kernel 1: LUT-conv (paired n) -> H fp32 + fp16 B tile -> fp16 HMMA -> e
// 16 warps: 4 (m) x 4 (n), warp tile 32x32
// ---------------------------------------------------------------------------
__global__ __launch_bounds__(TPB, 1) void k1_conv_attn(
    const int* __restrict__ seq, const float* __restrict__ va)
{
    extern __shared__ char sm[];
    const uint32_t smb = smem_u32(sm);
    float* sP   = (float*)(sm + OFF_SP);
    float* sv   = (float*)(sm + OFF_SV);
    int*   sseq = (int*)(sm + OFF_SSEQ);
    float* ep   = (float*)(sm + OFF_EP);

    const int tid = threadIdx.x;
    const int wid = tid >> 5, lane = tid & 31;
    const int t = blockIdx.x, b = blockIdx.y;

    // A tile: straight copy of pre-converted, pre-pitched W_a (L2-resident)
    {
        const uint4* Ah = (const uint4*)g_Wh;
        uint4* dA = (uint4*)(sm + OFF_A);
        #pragma unroll
        for (int i = tid; i < DDIM * PITCH / 8; i += TPB) dA[i] = Ah[i];
    }

    // small tables
    for (int i = tid; i < NCH * 3 * PSTRIDE; i += TPB) sP[i] = g_P[i];
    if (tid < 128) sv[tid] = va[tid];
    for (int i = tid; i < 4 * 130; i += TPB) {
        int s = i / 130, j = i % 130;
        sseq[i] = seq[b * SEQLEN + s * NL + t * NTILE + j];
    }
    __syncthreads();

    // conv via LUT + relu, paired n -> g_H (float2) + B tile (fp16x2)
    {
        const int n0 = (tid & 63) * 2;
        const int cs0 = tid >> 6;   // 0..7
        float* Hbase = g_H + (size_t)b * DDIM * NL + (size_t)t * NTILE + n0;
        #pragma unroll
        for (int s = 0; s < 4; s++) {
            const int l0 = sseq[s * 130 + n0];
            const int l1 = sseq[s * 130 + n0 + 1];
            const int l2 = sseq[s * 130 + n0 + 2];
            const int l3 = sseq[s * 130 + n0 + 3];
            #pragma unroll
            for (int jj = 0; jj < 4; jj++) {
                const int c = cs0 + 8 * jj;
                const float* Pc = sP + c * 3 * PSTRIDE;
                float a0 = Pc[l0] + Pc[PSTRIDE + l1] + Pc[2 * PSTRIDE + l2];
                float a1 = Pc[l1] + Pc[PSTRIDE + l2] + Pc[2 * PSTRIDE + l3];
                a0 = fmaxf(a0, 0.f);
                a1 = fmaxf(a1, 0.f);
                const int e = c * 4 + s;
                *(float2*)&Hbase[(size_t)e * NL] = make_float2(a0, a1);
                uint32_t o = (uint32_t)(e * PITCH + n0) * 2;
                *(__half2*)(sm + OFF_B + o) = __float22half2_rn(make_float2(a0, a1));
            }
        }
    }
    __syncthreads();

    // ---------------- GEMM: M[d][n] = Wa @ H, fp16 in, fp32 accum ----------
    const int wm = (wid & 3) * 32;
    const int wn = (wid >> 2) * 32;
    const int qd = lane >> 3, r8 = lane & 7;

    float c[2][4][4];
    #pragma unroll
    for (int mt = 0; mt < 2; mt++)
        #pragma unroll
        for (int nt = 0; nt < 4; nt++)
            #pragma unroll
            for (int q = 0; q < 4; q++) c[mt][nt][q] = 0.f;

    #pragma unroll
    for (int ks = 0; ks < 8; ks++) {
        const int k0 = ks * 16;
        uint32_t af[2][4];
        #pragma unroll
        for (int mt = 0; mt < 2; mt++) {
            uint32_t addr = smb + OFF_A +
                (uint32_t)((wm + mt * 16 + r8 + (qd & 1) * 8) * PITCH + k0 + (qd >> 1) * 8) * 2;
            LDSM_X4(af[mt], addr);
        }
        uint32_t bf[2][4];
        #pragma unroll
        for (int nb = 0; nb < 2; nb++) {
            uint32_t addr = smb + OFF_B +
                (uint32_t)((k0 + r8 + (qd & 1) * 8) * PITCH + wn + nb * 16 + (qd >> 1) * 8) * 2;
            LDSM_X4_T(bf[nb], addr);
        }
        #pragma unroll
        for (int mt = 0; mt < 2; mt++)
            #pragma unroll
            for (int nt = 0; nt < 4; nt++) {
                const int nb = nt >> 1, p = (nt & 1) * 2;
                MMA_F16(c[mt][nt], af[mt], bf[nb][p], bf[nb][p + 1]);
            }
    }

    // ---------------- epilogue: e[n] = sum_d v[d]*tanh(M[d][n]) ------------
    {
        const int g = lane >> 2, tq = lane & 3;
        #pragma unroll
        for (int nt = 0; nt < 4; nt++) {
            #pragma unroll
            for (int j = 0; j < 2; j++) {
                float s = 0.f;
                #pragma unroll
                for (int mt = 0; mt < 2; mt++) {
                    int d0 = wm + mt * 16 + g;
                    s += sv[d0]     * ftanh(c[mt][nt][j]);
                    s += sv[d0 + 8] * ftanh(c[mt][nt][2 + j]);
                }
                s += __shfl_xor_sync(0xffffffffu, s, 4);
                s += __shfl_xor_sync(0xffffffffu, s, 8);
                s += __shfl_xor_sync(0xffffffffu, s, 16);
                if (g == 0)
                    ep[(wid & 3) * 128 + wn + nt * 8 + tq * 2 + j] = s;
            }
        }
    }
    __syncthreads();
    if (tid < 128)
        g_e[b * NL + t * NTILE + tid] =
            (ep[tid] + ep[128 + tid]) + (ep[256 + tid] + ep[384 + tid]);
}

// ---------------------------------------------------------------------------
// Kernel 2: stable softmax per batch
// ---------------------------------------------------------------------------
__global__ __launch_bounds__(256) void k2_softmax()
{
    __shared__ float red[256];
    const int b = blockIdx.x, tid = threadIdx.x;
    float vals[8];
    float vmax = -1e30f;
    #pragma unroll
    for (int j = 0; j < 8; j++) {
        vals[j] = g_e[b * NL + tid + 256 * j];
        vmax = fmaxf(vmax, vals[j]);
    }
    red[tid] = vmax; __syncthreads();
    for (int off = 128; off > 0; off >>= 1) {
        if (tid < off) red[tid] = fmaxf(red[tid], red[tid + off]);
        __syncthreads();
    }
    vmax = red[0]; __syncthreads();
    float ssum = 0.f;
    #pragma unroll
    for (int j = 0; j < 8; j++) { vals[j] = __expf(vals[j] - vmax); ssum += vals[j]; }
    red[tid] = ssum; __syncthreads();
    for (int off = 128; off > 0; off >>= 1) {
        if (tid < off) red[tid] += red[tid + off];
        __syncthreads();
    }
    float inv = __fdividef(1.f, red[0]);
    #pragma unroll
    for (int j = 0; j < 8; j++) g_w[b * NL + tid + 256 * j] = vals[j] * inv;
}

// ---------------------------------------------------------------------------
// Kernel 3: ctx[b][d] = sum_n w[b][n] * H[b][d][n]   (DRAM-bound GEMV)
// grid (16, BATCH): 8 d-rows per CTA, one warp per d-row; streaming H loads
// ---------------------------------------------------------------------------
__global__ __launch_bounds__(256, 4) void k3_ctx(float* __restrict__ out)
{
    __shared__ float sw_[NL];
    const int tid = threadIdx.x;
    const int dc = blockIdx.x, b = blockIdx.y;

    const float4* Wg = (const float4*)(g_w + b * NL);
    float4* Ws = (float4*)sw_;
    #pragma unroll
    for (int i = tid; i < NL / 4; i += 256) Ws[i] = Wg[i];
    __syncthreads();

    const int dl = tid >> 5, hh = tid & 31;
    const int d = dc * 8 + dl;
    const float4* Hp = (const float4*)(g_H + (size_t)(b * DDIM + d) * NL);
    float s = 0.f;
    #pragma unroll
    for (int j = 0; j < 16; j++) {
        int n4 = hh + j * 32;
        float4 hv = __ldcs(Hp + n4);
        float4 wv = Ws[n4];
        s += hv.x * wv.x + hv.y * wv.y + hv.z * wv.z + hv.w * wv.w;
    }
    #pragma unroll
    for (int off = 16; off > 0; off >>= 1) s += __shfl_down_sync(0xffffffffu, s, off);
    if (hh == 0) out[b * DDIM + d] = s;
}

// ---------------------------------------------------------------------------
extern "C" void kernel_launch(void* const* d_in, const int* in_sizes, int n_in,
                              void* d_out, int out_size)
{
    const int*   seq = (const int*)d_in[0];
    const float* emb = (const float*)d_in[1];
    const float* cw  = (const float*)d_in[2];
    const float* cb  = (const float*)d_in[3];
    const float* Wa  = (const float*)d_in[4];
    const float* va  = (const float*)d_in[5];
    float* out = (float*)d_out;

    cudaFuncSetAttribute(k1_conv_attn, cudaFuncAttributeMaxDynamicSharedMemorySize, SM1_BYTES);

    k0_prep<<<(DDIM * DDIM + NCH * 3 * 26 + 255) / 256, 256>>>(Wa, emb, cw, cb);
    k1_conv_attn<<<dim3(NT, BATCH), TPB, SM1_BYTES>>>(seq, va);
    k2_softmax<<<BATCH, 256>>>();
    k3_ctx<<<dim3(16, BATCH), 256>>>(out);
}